// round 12
// baseline (speedup 1.0000x reference)
#include <cuda_runtime.h>
#include <cuda_bf16.h>
#include <cuda_fp16.h>
#include <cstdint>

#define N_NODES 100000
#define N_EDGES 3200000
#define F_IN 512
#define F_HID 64
#define F_OUT 20
#define SCAN_BLK 1024
#define N_SCANB ((N_NODES + SCAN_BLK - 1) / SCAN_BLK)  // 98

typedef unsigned long long u64;

// ---------------- scratch ----------------
__device__ __align__(256) float g_dinv[N_NODES];
__device__ __align__(256) int g_cnt[N_NODES];
__device__ __align__(256) int g_rowstart[N_NODES];
__device__ __align__(256) int g_cursor[N_NODES];
__device__ __align__(256) int g_bsum[N_SCANB];
__device__ __align__(256) int g_boff[N_SCANB];
__device__ __align__(256) float2 g_edge[N_EDGES];        // (src bits, ew) raw
__device__ __align__(256) __half2 g_xw1h[N_NODES * 32];  // x @ W1, fp16 pairs
__device__ __align__(256) __half g_h2h[N_NODES * 32];    // relu(agg1) @ W2, fp16, stride 32

__device__ __forceinline__ uint32_t smem_u32(const void* p) {
    uint32_t a;
    asm("{ .reg .u64 t; cvta.to.shared.u64 t, %1; cvt.u32.u64 %0, t; }" : "=r"(a) : "l"(p));
    return a;
}

#define LDMATRIX_X4(r0, r1, r2, r3, addr)                                        \
    asm volatile("ldmatrix.sync.aligned.m8n8.x4.shared.b16 {%0,%1,%2,%3}, [%4];" \
                 : "=r"(r0), "=r"(r1), "=r"(r2), "=r"(r3) : "r"(addr))
#define LDMATRIX_X4_T(r0, r1, r2, r3, addr)                                            \
    asm volatile("ldmatrix.sync.aligned.m8n8.x4.trans.shared.b16 {%0,%1,%2,%3}, [%4];" \
                 : "=r"(r0), "=r"(r1), "=r"(r2), "=r"(r3) : "r"(addr))
#define MMA_BF16(c0, c1, c2, c3, a0, a1, a2, a3, b0, b1)                          \
    asm volatile(                                                                 \
        "mma.sync.aligned.m16n8k16.row.col.f32.bf16.bf16.f32 "                    \
        "{%0,%1,%2,%3}, {%4,%5,%6,%7}, {%8,%9}, {%0,%1,%2,%3};"                   \
        : "+f"(c0), "+f"(c1), "+f"(c2), "+f"(c3)                                  \
        : "r"(a0), "r"(a1), "r"(a2), "r"(a3), "r"(b0), "r"(b1))

// ---------------- GEMM1: xw1 = x @ W1, pure bf16 tensor cores, pipelined ----------------
#define A_STRIDE 40
#define B_STRIDE 72
#define N_KCHUNK (F_IN / 32)
__global__ __launch_bounds__(256, 2) void gemm1_tc_kernel(const float* __restrict__ x,
                                                          const float* __restrict__ W1) {
    __shared__ __nv_bfloat16 a_sm[128 * A_STRIDE];
    __shared__ __nv_bfloat16 b_sm[32 * B_STRIDE];

    const int tid = threadIdx.x;
    const int wid = tid >> 5;
    const int lane = tid & 31;
    const int nb = blockIdx.x * 128;

    float c[8][4];
#pragma unroll
    for (int j = 0; j < 8; j++)
#pragma unroll
        for (int q = 0; q < 4; q++) c[j][q] = 0.f;

    const int a_row = wid * 16 + (lane & 15);
    const int a_koff = (lane >> 4) * 8;
    const uint32_t a_addr = smem_u32(&a_sm[a_row * A_STRIDE + a_koff]);
    const int b_k = lane & 15;
    const int b_noff = (lane >> 4) * 8;
    const uint32_t b_base = smem_u32(&b_sm[b_k * B_STRIDE + b_noff]);

    const int ar[4] = {(tid + 0) >> 3, (tid + 256) >> 3, (tid + 512) >> 3, (tid + 768) >> 3};
    const int ac = (tid & 7) * 4;
    const int br[2] = {tid >> 4, (tid + 256) >> 4};
    const int bn = (tid & 15) * 4;

    float4 pa[4], pb[2];

#pragma unroll
    for (int j = 0; j < 4; j++) {
        int node = nb + ar[j];
        pa[j] = (node < N_NODES) ? *(const float4*)&x[(size_t)node * F_IN + ac]
                                 : make_float4(0.f, 0.f, 0.f, 0.f);
    }
#pragma unroll
    for (int j = 0; j < 2; j++) pb[j] = *(const float4*)&W1[(size_t)br[j] * F_HID + bn];

    for (int kc = 0; kc < N_KCHUNK; kc++) {
#pragma unroll
        for (int j = 0; j < 4; j++) {
            float4 v = pa[j];
            int r = ar[j];
            *(__nv_bfloat162*)&a_sm[r * A_STRIDE + ac] = __floats2bfloat162_rn(v.x, v.y);
            *(__nv_bfloat162*)&a_sm[r * A_STRIDE + ac + 2] = __floats2bfloat162_rn(v.z, v.w);
        }
#pragma unroll
        for (int j = 0; j < 2; j++) {
            float4 w = pb[j];
            int r = br[j];
            *(__nv_bfloat162*)&b_sm[r * B_STRIDE + bn] = __floats2bfloat162_rn(w.x, w.y);
            *(__nv_bfloat162*)&b_sm[r * B_STRIDE + bn + 2] = __floats2bfloat162_rn(w.z, w.w);
        }
        __syncthreads();

        if (kc + 1 < N_KCHUNK) {
            const int k0n = (kc + 1) * 32;
#pragma unroll
            for (int j = 0; j < 4; j++) {
                int node = nb + ar[j];
                pa[j] = (node < N_NODES) ? *(const float4*)&x[(size_t)node * F_IN + k0n + ac]
                                         : make_float4(0.f, 0.f, 0.f, 0.f);
            }
#pragma unroll
            for (int j = 0; j < 2; j++)
                pb[j] = *(const float4*)&W1[(size_t)(k0n + br[j]) * F_HID + bn];
        }

#pragma unroll
        for (int ks = 0; ks < 2; ks++) {
            uint32_t ah[4];
            LDMATRIX_X4(ah[0], ah[1], ah[2], ah[3], a_addr + ks * 32);
            uint32_t bh[4][4];
#pragma unroll
            for (int nf = 0; nf < 4; nf++) {
                LDMATRIX_X4_T(bh[nf][0], bh[nf][1], bh[nf][2], bh[nf][3],
                              b_base + ks * (16 * B_STRIDE * 2) + nf * 32);
            }
#pragma unroll
            for (int nf = 0; nf < 4; nf++) {
                MMA_BF16(c[2 * nf][0], c[2 * nf][1], c[2 * nf][2], c[2 * nf][3],
                         ah[0], ah[1], ah[2], ah[3], bh[nf][0], bh[nf][1]);
                MMA_BF16(c[2 * nf + 1][0], c[2 * nf + 1][1], c[2 * nf + 1][2], c[2 * nf + 1][3],
                         ah[0], ah[1], ah[2], ah[3], bh[nf][2], bh[nf][3]);
            }
        }
        __syncthreads();
    }

    const int g = lane >> 2;
    const int cl = (lane & 3) * 2;
    const int row0 = nb + wid * 16 + g;
    const int row1 = row0 + 8;
#pragma unroll
    for (int j = 0; j < 8; j++) {
        int col2 = (j * 8 + cl) >> 1;
        if (row0 < N_NODES) g_xw1h[(size_t)row0 * 32 + col2] = __floats2half2_rn(c[j][0], c[j][1]);
        if (row1 < N_NODES) g_xw1h[(size_t)row1 * 32 + col2] = __floats2half2_rn(c[j][2], c[j][3]);
    }
}

// ---------------- init ----------------
__global__ void init_kernel() {
    int i = blockIdx.x * blockDim.x + threadIdx.x;
    if (i < N_NODES) g_cnt[i] = 0;
}

// int-only count pass (reads dst only)
__global__ void cnt_accum_kernel(const int* __restrict__ dst) {
    int e = blockIdx.x * blockDim.x + threadIdx.x;
    if (e < N_EDGES) atomicAdd(&g_cnt[dst[e]], 1);
}

// ---------------- scan ----------------
__global__ void scan1_kernel() {
    __shared__ int sh[SCAN_BLK];
    int i = blockIdx.x * SCAN_BLK + threadIdx.x;
    int t = threadIdx.x;
    int v = (i < N_NODES) ? g_cnt[i] : 0;
    sh[t] = v;
    __syncthreads();
#pragma unroll
    for (int off = 1; off < SCAN_BLK; off <<= 1) {
        int u = (t >= off) ? sh[t - off] : 0;
        __syncthreads();
        sh[t] += u;
        __syncthreads();
    }
    if (i < N_NODES) g_rowstart[i] = sh[t] - v;
    if (t == SCAN_BLK - 1) g_bsum[blockIdx.x] = sh[t];
}

__global__ void scan2_kernel() {
    __shared__ int sh[128];
    int t = threadIdx.x;
    int v = (t < N_SCANB) ? g_bsum[t] : 0;
    sh[t] = v;
    __syncthreads();
#pragma unroll
    for (int off = 1; off < 128; off <<= 1) {
        int u = (t >= off) ? sh[t - off] : 0;
        __syncthreads();
        sh[t] += u;
        __syncthreads();
    }
    if (t < N_SCANB) g_boff[t] = sh[t] - v;
}

__global__ void scan3_kernel() {
    int i = blockIdx.x * blockDim.x + threadIdx.x;
    if (i < N_NODES) {
        int rs = g_rowstart[i] + g_boff[i / SCAN_BLK];
        g_rowstart[i] = rs;
        g_cursor[i] = rs;
    }
}

// fill raw (src, ew) — no dinv dependency
__global__ void fill_kernel(const int* __restrict__ src, const int* __restrict__ dst,
                            const float* __restrict__ ew) {
    int e = blockIdx.x * blockDim.x + threadIdx.x;
    if (e >= N_EDGES) return;
    int s = src[e];
    int d = dst[e];
    int slot = atomicAdd(&g_cursor[d], 1);
    g_edge[slot] = make_float2(__int_as_float(s), ew[e]);
}

// dinv from CSR: warp per node, linear row sum of ew
__global__ __launch_bounds__(256) void dinv_csr_kernel() {
    int n = (blockIdx.x * blockDim.x + threadIdx.x) >> 5;
    int lane = threadIdx.x & 31;
    if (n >= N_NODES) return;
    int beg = g_rowstart[n];
    int end = beg + g_cnt[n];
    float sum = 0.f;
    for (int i = beg + lane; i < end; i += 32) sum += g_edge[i].y;
#pragma unroll
    for (int o = 16; o > 0; o >>= 1) sum += __shfl_xor_sync(0xFFFFFFFF, sum, o);
    if (lane == 0) g_dinv[n] = rsqrtf(1.0f + sum);
}

// ---------------- agg1 + gemm2 fused: 8 warps = 8 nodes per block ----------------
// cooperative edge staging: 32 lanes load 32 edges + dinv[s], then shfl-broadcast.
__global__ __launch_bounds__(256) void agg1_gemm2_kernel(const float* __restrict__ b1,
                                                         const float* __restrict__ W2) {
    __shared__ float hs[8][68];
    __shared__ float ws[64][20];
    const int tid = threadIdx.x;
    const int w = tid >> 5;
    const int lane = tid & 31;
    const int n = blockIdx.x * 8 + w;

#pragma unroll
    for (int i = tid; i < 64 * 20; i += 256) ws[i / 20][i % 20] = W2[i];

    if (n < N_NODES) {
        int i = g_rowstart[n];
        const int end = i + g_cnt[n];
        float2 acc = make_float2(0.f, 0.f);
        while (i < end) {
            int m = end - i;
            if (m > 32) m = 32;
            int s_l = 0;
            float nm_l = 0.f;
            if (lane < m) {
                float2 ep = g_edge[i + lane];
                s_l = __float_as_int(ep.x);
                nm_l = ep.y * g_dinv[s_l];
            }
            if (m == 32) {
#pragma unroll 8
                for (int j = 0; j < 32; j++) {
                    int s = __shfl_sync(0xFFFFFFFF, s_l, j);
                    float nm = __shfl_sync(0xFFFFFFFF, nm_l, j);
                    float2 v = __half22float2(g_xw1h[(size_t)s * 32 + lane]);
                    acc.x = fmaf(nm, v.x, acc.x);
                    acc.y = fmaf(nm, v.y, acc.y);
                }
            } else {
                for (int j = 0; j < m; j++) {
                    int s = __shfl_sync(0xFFFFFFFF, s_l, j);
                    float nm = __shfl_sync(0xFFFFFFFF, nm_l, j);
                    float2 v = __half22float2(g_xw1h[(size_t)s * 32 + lane]);
                    acc.x = fmaf(nm, v.x, acc.x);
                    acc.y = fmaf(nm, v.y, acc.y);
                }
            }
            i += m;
        }
        float di = g_dinv[n];
        float dd = di * di;
        float2 xv = __half22float2(g_xw1h[(size_t)n * 32 + lane]);
        float2 bv = *(const float2*)&b1[lane * 2];
        hs[w][lane * 2] = fmaxf(bv.x + dd * xv.x + di * acc.x, 0.f);
        hs[w][lane * 2 + 1] = fmaxf(bv.y + dd * xv.y + di * acc.y, 0.f);
    }
    __syncthreads();

    if (tid < 160) {
        int nn = tid / 20;
        int o = tid % 20;
        int node = blockIdx.x * 8 + nn;
        if (node < N_NODES) {
            float acc = 0.f;
#pragma unroll
            for (int k = 0; k < 64; k++) acc = fmaf(hs[nn][k], ws[k][o], acc);
            g_h2h[(size_t)node * 32 + o] = __float2half(acc);
        }
    }
}

// ---------------- agg2 + softmax ----------------
__global__ __launch_bounds__(256) void agg2_kernel(const float* __restrict__ b2,
                                                   float* __restrict__ out) {
    int warp = (blockIdx.x * blockDim.x + threadIdx.x) >> 5;
    int lane = threadIdx.x & 31;
    if (warp >= N_NODES) return;
    int n = warp;
    int i = g_rowstart[n];
    const int end = i + g_cnt[n];
    int col = (lane < F_OUT) ? lane : 0;
    float acc = 0.f;
    while (i < end) {
        int m = end - i;
        if (m > 32) m = 32;
        int s_l = 0;
        float nm_l = 0.f;
        if (lane < m) {
            float2 ep = g_edge[i + lane];
            s_l = __float_as_int(ep.x);
            nm_l = ep.y * g_dinv[s_l];
        }
        if (m == 32) {
#pragma unroll 8
            for (int j = 0; j < 32; j++) {
                int s = __shfl_sync(0xFFFFFFFF, s_l, j);
                float nm = __shfl_sync(0xFFFFFFFF, nm_l, j);
                acc = fmaf(nm, __half2float(g_h2h[(size_t)s * 32 + col]), acc);
            }
        } else {
            for (int j = 0; j < m; j++) {
                int s = __shfl_sync(0xFFFFFFFF, s_l, j);
                float nm = __shfl_sync(0xFFFFFFFF, nm_l, j);
                acc = fmaf(nm, __half2float(g_h2h[(size_t)s * 32 + col]), acc);
            }
        }
        i += m;
    }
    float di = g_dinv[n];
    float dd = di * di;
    float val = -1e30f;
    if (lane < F_OUT)
        val = b2[lane] + dd * __half2float(g_h2h[(size_t)n * 32 + lane]) + di * acc;
    float m = val;
#pragma unroll
    for (int o = 16; o > 0; o >>= 1) m = fmaxf(m, __shfl_xor_sync(0xFFFFFFFF, m, o));
    float ex = (lane < F_OUT) ? __expf(val - m) : 0.f;
    float s = ex;
#pragma unroll
    for (int o = 16; o > 0; o >>= 1) s += __shfl_xor_sync(0xFFFFFFFF, s, o);
    if (lane < F_OUT) out[(size_t)n * F_OUT + lane] = ex / s;
}

// ---------------- launch ----------------
extern "C" void kernel_launch(void* const* d_in, const int* in_sizes, int n_in,
                              void* d_out, int out_size) {
    const float* x = (const float*)d_in[0];
    const int* ei = (const int*)d_in[1];
    const float* ew = (const float*)d_in[2];
    const float* W1 = (const float*)d_in[3];
    const float* b1 = (const float*)d_in[4];
    const float* W2 = (const float*)d_in[5];
    const float* b2 = (const float*)d_in[6];
    float* out = (float*)d_out;

    const int* src = ei;
    const int* dst = ei + N_EDGES;

    init_kernel<<<(N_NODES + 255) / 256, 256>>>();
    cnt_accum_kernel<<<(N_EDGES + 255) / 256, 256>>>(dst);
    scan1_kernel<<<N_SCANB, SCAN_BLK>>>();
    gemm1_tc_kernel<<<(N_NODES + 127) / 128, 256>>>(x, W1);  // slot 3: gets profiled
    scan2_kernel<<<1, 128>>>();
    scan3_kernel<<<(N_NODES + 255) / 256, 256>>>();
    fill_kernel<<<(N_EDGES + 255) / 256, 256>>>(src, dst, ew);
    dinv_csr_kernel<<<(N_NODES * 32 + 255) / 256, 256>>>();

    agg1_gemm2_kernel<<<(N_NODES + 7) / 8, 256>>>(b1, W2);
    agg2_kernel<<<(N_NODES * 32 + 255) / 256, 256>>>(b2, out);
}

// round 13
// speedup vs baseline: 1.0638x; 1.0638x over previous
#include <cuda_runtime.h>
#include <cuda_bf16.h>
#include <cuda_fp16.h>
#include <cstdint>

#define N_NODES 100000
#define N_EDGES 3200000
#define F_IN 512
#define F_HID 64
#define F_OUT 20
#define SCAN_BLK 1024
#define N_SCANB ((N_NODES + SCAN_BLK - 1) / SCAN_BLK)  // 98

typedef unsigned long long u64;

// ---------------- scratch ----------------
__device__ __align__(256) float g_deg[N_NODES];
__device__ __align__(256) float g_dinv[N_NODES];
__device__ __align__(256) int g_cnt[N_NODES];
__device__ __align__(256) int g_rowstart[N_NODES];
__device__ __align__(256) int g_cursor[N_NODES];
__device__ __align__(256) int g_bsum[N_SCANB];
__device__ __align__(256) int g_boff[N_SCANB];
__device__ __align__(256) float2 g_edge[N_EDGES];        // (src bits, norm)
__device__ __align__(256) __half2 g_xw1h[N_NODES * 32];  // x @ W1, fp16 pairs
__device__ __align__(256) __half g_h2h[N_NODES * 32];    // relu(agg1) @ W2, fp16, stride 32

__device__ __forceinline__ uint32_t smem_u32(const void* p) {
    uint32_t a;
    asm("{ .reg .u64 t; cvta.to.shared.u64 t, %1; cvt.u32.u64 %0, t; }" : "=r"(a) : "l"(p));
    return a;
}

#define LDMATRIX_X4(r0, r1, r2, r3, addr)                                        \
    asm volatile("ldmatrix.sync.aligned.m8n8.x4.shared.b16 {%0,%1,%2,%3}, [%4];" \
                 : "=r"(r0), "=r"(r1), "=r"(r2), "=r"(r3) : "r"(addr))
#define LDMATRIX_X4_T(r0, r1, r2, r3, addr)                                            \
    asm volatile("ldmatrix.sync.aligned.m8n8.x4.trans.shared.b16 {%0,%1,%2,%3}, [%4];" \
                 : "=r"(r0), "=r"(r1), "=r"(r2), "=r"(r3) : "r"(addr))
#define MMA_BF16(c0, c1, c2, c3, a0, a1, a2, a3, b0, b1)                          \
    asm volatile(                                                                 \
        "mma.sync.aligned.m16n8k16.row.col.f32.bf16.bf16.f32 "                    \
        "{%0,%1,%2,%3}, {%4,%5,%6,%7}, {%8,%9}, {%0,%1,%2,%3};"                   \
        : "+f"(c0), "+f"(c1), "+f"(c2), "+f"(c3)                                  \
        : "r"(a0), "r"(a1), "r"(a2), "r"(a3), "r"(b0), "r"(b1))

// ---------------- GEMM1: xw1 = x @ W1, pure bf16 tensor cores, pipelined ----------------
#define A_STRIDE 40
#define B_STRIDE 72
#define N_KCHUNK (F_IN / 32)
__global__ __launch_bounds__(256, 2) void gemm1_tc_kernel(const float* __restrict__ x,
                                                          const float* __restrict__ W1) {
    __shared__ __nv_bfloat16 a_sm[128 * A_STRIDE];
    __shared__ __nv_bfloat16 b_sm[32 * B_STRIDE];

    const int tid = threadIdx.x;
    const int wid = tid >> 5;
    const int lane = tid & 31;
    const int nb = blockIdx.x * 128;

    float c[8][4];
#pragma unroll
    for (int j = 0; j < 8; j++)
#pragma unroll
        for (int q = 0; q < 4; q++) c[j][q] = 0.f;

    const int a_row = wid * 16 + (lane & 15);
    const int a_koff = (lane >> 4) * 8;
    const uint32_t a_addr = smem_u32(&a_sm[a_row * A_STRIDE + a_koff]);
    const int b_k = lane & 15;
    const int b_noff = (lane >> 4) * 8;
    const uint32_t b_base = smem_u32(&b_sm[b_k * B_STRIDE + b_noff]);

    const int ar[4] = {(tid + 0) >> 3, (tid + 256) >> 3, (tid + 512) >> 3, (tid + 768) >> 3};
    const int ac = (tid & 7) * 4;
    const int br[2] = {tid >> 4, (tid + 256) >> 4};
    const int bn = (tid & 15) * 4;

    float4 pa[4], pb[2];

#pragma unroll
    for (int j = 0; j < 4; j++) {
        int node = nb + ar[j];
        pa[j] = (node < N_NODES) ? *(const float4*)&x[(size_t)node * F_IN + ac]
                                 : make_float4(0.f, 0.f, 0.f, 0.f);
    }
#pragma unroll
    for (int j = 0; j < 2; j++) pb[j] = *(const float4*)&W1[(size_t)br[j] * F_HID + bn];

    for (int kc = 0; kc < N_KCHUNK; kc++) {
#pragma unroll
        for (int j = 0; j < 4; j++) {
            float4 v = pa[j];
            int r = ar[j];
            *(__nv_bfloat162*)&a_sm[r * A_STRIDE + ac] = __floats2bfloat162_rn(v.x, v.y);
            *(__nv_bfloat162*)&a_sm[r * A_STRIDE + ac + 2] = __floats2bfloat162_rn(v.z, v.w);
        }
#pragma unroll
        for (int j = 0; j < 2; j++) {
            float4 w = pb[j];
            int r = br[j];
            *(__nv_bfloat162*)&b_sm[r * B_STRIDE + bn] = __floats2bfloat162_rn(w.x, w.y);
            *(__nv_bfloat162*)&b_sm[r * B_STRIDE + bn + 2] = __floats2bfloat162_rn(w.z, w.w);
        }
        __syncthreads();

        if (kc + 1 < N_KCHUNK) {
            const int k0n = (kc + 1) * 32;
#pragma unroll
            for (int j = 0; j < 4; j++) {
                int node = nb + ar[j];
                pa[j] = (node < N_NODES) ? *(const float4*)&x[(size_t)node * F_IN + k0n + ac]
                                         : make_float4(0.f, 0.f, 0.f, 0.f);
            }
#pragma unroll
            for (int j = 0; j < 2; j++)
                pb[j] = *(const float4*)&W1[(size_t)(k0n + br[j]) * F_HID + bn];
        }

#pragma unroll
        for (int ks = 0; ks < 2; ks++) {
            uint32_t ah[4];
            LDMATRIX_X4(ah[0], ah[1], ah[2], ah[3], a_addr + ks * 32);
            uint32_t bh[4][4];
#pragma unroll
            for (int nf = 0; nf < 4; nf++) {
                LDMATRIX_X4_T(bh[nf][0], bh[nf][1], bh[nf][2], bh[nf][3],
                              b_base + ks * (16 * B_STRIDE * 2) + nf * 32);
            }
#pragma unroll
            for (int nf = 0; nf < 4; nf++) {
                MMA_BF16(c[2 * nf][0], c[2 * nf][1], c[2 * nf][2], c[2 * nf][3],
                         ah[0], ah[1], ah[2], ah[3], bh[nf][0], bh[nf][1]);
                MMA_BF16(c[2 * nf + 1][0], c[2 * nf + 1][1], c[2 * nf + 1][2], c[2 * nf + 1][3],
                         ah[0], ah[1], ah[2], ah[3], bh[nf][2], bh[nf][3]);
            }
        }
        __syncthreads();
    }

    const int g = lane >> 2;
    const int cl = (lane & 3) * 2;
    const int row0 = nb + wid * 16 + g;
    const int row1 = row0 + 8;
#pragma unroll
    for (int j = 0; j < 8; j++) {
        int col2 = (j * 8 + cl) >> 1;
        if (row0 < N_NODES) g_xw1h[(size_t)row0 * 32 + col2] = __floats2half2_rn(c[j][0], c[j][1]);
        if (row1 < N_NODES) g_xw1h[(size_t)row1 * 32 + col2] = __floats2half2_rn(c[j][2], c[j][3]);
    }
}

// ---------------- init ----------------
__global__ void init_kernel() {
    int i = blockIdx.x * blockDim.x + threadIdx.x;
    if (i < N_NODES) {
        g_deg[i] = 1.0f;
        g_cnt[i] = 0;
    }
}

__global__ void deg_accum_kernel(const int* __restrict__ dst,
                                 const float* __restrict__ ew) {
    int e = blockIdx.x * blockDim.x + threadIdx.x;
    if (e < N_EDGES) {
        int d = dst[e];
        atomicAdd(&g_deg[d], ew[e]);
        atomicAdd(&g_cnt[d], 1);
    }
}

// ---------------- scan ----------------
__global__ void scan1_kernel() {
    __shared__ int sh[SCAN_BLK];
    int i = blockIdx.x * SCAN_BLK + threadIdx.x;
    int t = threadIdx.x;
    int v = (i < N_NODES) ? g_cnt[i] : 0;
    sh[t] = v;
    __syncthreads();
#pragma unroll
    for (int off = 1; off < SCAN_BLK; off <<= 1) {
        int u = (t >= off) ? sh[t - off] : 0;
        __syncthreads();
        sh[t] += u;
        __syncthreads();
    }
    if (i < N_NODES) g_rowstart[i] = sh[t] - v;
    if (t == SCAN_BLK - 1) g_bsum[blockIdx.x] = sh[t];
}

__global__ void scan2_kernel() {
    __shared__ int sh[128];
    int t = threadIdx.x;
    int v = (t < N_SCANB) ? g_bsum[t] : 0;
    sh[t] = v;
    __syncthreads();
#pragma unroll
    for (int off = 1; off < 128; off <<= 1) {
        int u = (t >= off) ? sh[t - off] : 0;
        __syncthreads();
        sh[t] += u;
        __syncthreads();
    }
    if (t < N_SCANB) g_boff[t] = sh[t] - v;
}

// scan3 + dinv + cursor init fused
__global__ void scan3_kernel() {
    int i = blockIdx.x * blockDim.x + threadIdx.x;
    if (i < N_NODES) {
        int rs = g_rowstart[i] + g_boff[i / SCAN_BLK];
        g_rowstart[i] = rs;
        g_cursor[i] = rs;
        g_dinv[i] = rsqrtf(g_deg[i]);
    }
}

__global__ void fill_kernel(const int* __restrict__ src, const int* __restrict__ dst,
                            const float* __restrict__ ew) {
    int e = blockIdx.x * blockDim.x + threadIdx.x;
    if (e >= N_EDGES) return;
    int s = src[e];
    int d = dst[e];
    float nm = g_dinv[s] * ew[e] * g_dinv[d];
    int slot = atomicAdd(&g_cursor[d], 1);
    g_edge[slot] = make_float2(__int_as_float(s), nm);
}

// ---------------- agg1 + gemm2 fused: 8 warps = 8 nodes per block ----------------
__global__ __launch_bounds__(256) void agg1_gemm2_kernel(const float* __restrict__ b1,
                                                         const float* __restrict__ W2) {
    __shared__ float hs[8][68];
    __shared__ float ws[64][20];
    const int tid = threadIdx.x;
    const int w = tid >> 5;
    const int lane = tid & 31;
    const int n = blockIdx.x * 8 + w;

#pragma unroll
    for (int i = tid; i < 64 * 20; i += 256) ws[i / 20][i % 20] = W2[i];

    if (n < N_NODES) {
        int i = g_rowstart[n];
        int end = i + g_cnt[n];
        float2 acc = make_float2(0.f, 0.f);
        for (; i + 4 <= end; i += 4) {
            float2 e0 = g_edge[i], e1 = g_edge[i + 1], e2 = g_edge[i + 2], e3 = g_edge[i + 3];
            float2 v0 = __half22float2(g_xw1h[(size_t)__float_as_int(e0.x) * 32 + lane]);
            float2 v1 = __half22float2(g_xw1h[(size_t)__float_as_int(e1.x) * 32 + lane]);
            float2 v2 = __half22float2(g_xw1h[(size_t)__float_as_int(e2.x) * 32 + lane]);
            float2 v3 = __half22float2(g_xw1h[(size_t)__float_as_int(e3.x) * 32 + lane]);
            acc.x = fmaf(e0.y, v0.x, acc.x);
            acc.y = fmaf(e0.y, v0.y, acc.y);
            acc.x = fmaf(e1.y, v1.x, acc.x);
            acc.y = fmaf(e1.y, v1.y, acc.y);
            acc.x = fmaf(e2.y, v2.x, acc.x);
            acc.y = fmaf(e2.y, v2.y, acc.y);
            acc.x = fmaf(e3.y, v3.x, acc.x);
            acc.y = fmaf(e3.y, v3.y, acc.y);
        }
        for (; i < end; i++) {
            float2 ep = g_edge[i];
            float2 v = __half22float2(g_xw1h[(size_t)__float_as_int(ep.x) * 32 + lane]);
            acc.x = fmaf(ep.y, v.x, acc.x);
            acc.y = fmaf(ep.y, v.y, acc.y);
        }
        float di = g_dinv[n];
        float dd = di * di;
        float2 xv = __half22float2(g_xw1h[(size_t)n * 32 + lane]);
        float2 bv = *(const float2*)&b1[lane * 2];
        hs[w][lane * 2] = fmaxf(bv.x + dd * xv.x + acc.x, 0.f);
        hs[w][lane * 2 + 1] = fmaxf(bv.y + dd * xv.y + acc.y, 0.f);
    }
    __syncthreads();

    if (tid < 160) {
        int nn = tid / 20;
        int o = tid % 20;
        int node = blockIdx.x * 8 + nn;
        if (node < N_NODES) {
            float acc = 0.f;
#pragma unroll
            for (int k = 0; k < 64; k++) acc = fmaf(hs[nn][k], ws[k][o], acc);
            g_h2h[(size_t)node * 32 + o] = __float2half(acc);
        }
    }
}

// ---------------- agg2 + softmax ----------------
__global__ __launch_bounds__(256) void agg2_kernel(const float* __restrict__ b2,
                                                   float* __restrict__ out) {
    int warp = (blockIdx.x * blockDim.x + threadIdx.x) >> 5;
    int lane = threadIdx.x & 31;
    if (warp >= N_NODES) return;
    int n = warp;
    int i = g_rowstart[n];
    int end = i + g_cnt[n];
    int col = (lane < F_OUT) ? lane : 0;
    float acc = 0.f;
    for (; i + 4 <= end; i += 4) {
        float2 e0 = g_edge[i], e1 = g_edge[i + 1], e2 = g_edge[i + 2], e3 = g_edge[i + 3];
        float v0 = __half2float(g_h2h[(size_t)__float_as_int(e0.x) * 32 + col]);
        float v1 = __half2float(g_h2h[(size_t)__float_as_int(e1.x) * 32 + col]);
        float v2 = __half2float(g_h2h[(size_t)__float_as_int(e2.x) * 32 + col]);
        float v3 = __half2float(g_h2h[(size_t)__float_as_int(e3.x) * 32 + col]);
        acc = fmaf(e0.y, v0, acc);
        acc = fmaf(e1.y, v1, acc);
        acc = fmaf(e2.y, v2, acc);
        acc = fmaf(e3.y, v3, acc);
    }
    for (; i < end; i++) {
        float2 ep = g_edge[i];
        acc = fmaf(ep.y, __half2float(g_h2h[(size_t)__float_as_int(ep.x) * 32 + col]), acc);
    }
    float di = g_dinv[n];
    float dd = di * di;
    float val = -1e30f;
    if (lane < F_OUT)
        val = b2[lane] + dd * __half2float(g_h2h[(size_t)n * 32 + lane]) + acc;
    float m = val;
#pragma unroll
    for (int o = 16; o > 0; o >>= 1) m = fmaxf(m, __shfl_xor_sync(0xFFFFFFFF, m, o));
    float ex = (lane < F_OUT) ? __expf(val - m) : 0.f;
    float s = ex;
#pragma unroll
    for (int o = 16; o > 0; o >>= 1) s += __shfl_xor_sync(0xFFFFFFFF, s, o);
    if (lane < F_OUT) out[(size_t)n * F_OUT + lane] = ex / s;
}

// ---------------- launch ----------------
extern "C" void kernel_launch(void* const* d_in, const int* in_sizes, int n_in,
                              void* d_out, int out_size) {
    const float* x = (const float*)d_in[0];
    const int* ei = (const int*)d_in[1];
    const float* ew = (const float*)d_in[2];
    const float* W1 = (const float*)d_in[3];
    const float* b1 = (const float*)d_in[4];
    const float* W2 = (const float*)d_in[5];
    const float* b2 = (const float*)d_in[6];
    float* out = (float*)d_out;

    const int* src = ei;
    const int* dst = ei + N_EDGES;

    // one-time infra (created on the uncaptured correctness call; reused during capture)
    static cudaStream_t s2 = nullptr;
    static cudaEvent_t ev_fork = nullptr, ev_join = nullptr;
    if (s2 == nullptr) {
        cudaStreamCreateWithFlags(&s2, cudaStreamNonBlocking);
        cudaEventCreateWithFlags(&ev_fork, cudaEventDisableTiming);
        cudaEventCreateWithFlags(&ev_join, cudaEventDisableTiming);
    }

    // fork: gemm1 on s2, overlapped with the CSR pre-pass on the main stream
    cudaEventRecord(ev_fork, 0);
    cudaStreamWaitEvent(s2, ev_fork, 0);
    gemm1_tc_kernel<<<(N_NODES + 127) / 128, 256, 0, s2>>>(x, W1);
    cudaEventRecord(ev_join, s2);

    // pre-pass chain (main stream)
    init_kernel<<<(N_NODES + 255) / 256, 256>>>();
    deg_accum_kernel<<<(N_EDGES + 255) / 256, 256>>>(dst, ew);
    scan1_kernel<<<N_SCANB, SCAN_BLK>>>();
    scan2_kernel<<<1, 128>>>();
    scan3_kernel<<<(N_NODES + 255) / 256, 256>>>();
    fill_kernel<<<(N_EDGES + 255) / 256, 256>>>(src, dst, ew);

    // join: agg1 needs both fill (main) and gemm1 (s2)
    cudaStreamWaitEvent(0, ev_join, 0);
    agg1_gemm2_kernel<<<(N_NODES + 7) / 8, 256>>>(b1, W2);
    agg2_kernel<<<(N_NODES * 32 + 255) / 256, 256>>>(b2, out);
}

// round 14
// speedup vs baseline: 1.0989x; 1.0330x over previous
#include <cuda_runtime.h>
#include <cuda_bf16.h>
#include <cuda_fp16.h>
#include <cstdint>

#define N_NODES 100000
#define N_EDGES 3200000
#define F_IN 512
#define F_HID 64
#define F_OUT 20
#define SCAN_BLK 1024
#define N_SCANB ((N_NODES + SCAN_BLK - 1) / SCAN_BLK)  // 98

typedef unsigned long long u64;

// ---------------- scratch ----------------
__device__ __align__(256) float g_deg[N_NODES];
__device__ __align__(256) float g_dinv[N_NODES];
__device__ __align__(256) int g_cnt[N_NODES];
__device__ __align__(256) int g_rowstart[N_NODES];
__device__ __align__(256) int g_cursor[N_NODES];
__device__ __align__(256) int g_bsum[N_SCANB];
__device__ __align__(256) int g_boff[N_SCANB];
__device__ __align__(256) float2 g_edge[N_EDGES];        // (src bits, norm)
__device__ __align__(256) __half2 g_xw1h[N_NODES * 32];  // x @ W1, fp16 pairs
__device__ __align__(256) __half g_h2h[N_NODES * 32];    // relu(agg1) @ W2, fp16, stride 32

__device__ __forceinline__ uint32_t smem_u32(const void* p) {
    uint32_t a;
    asm("{ .reg .u64 t; cvta.to.shared.u64 t, %1; cvt.u32.u64 %0, t; }" : "=r"(a) : "l"(p));
    return a;
}

#define LDMATRIX_X4(r0, r1, r2, r3, addr)                                        \
    asm volatile("ldmatrix.sync.aligned.m8n8.x4.shared.b16 {%0,%1,%2,%3}, [%4];" \
                 : "=r"(r0), "=r"(r1), "=r"(r2), "=r"(r3) : "r"(addr))
#define LDMATRIX_X4_T(r0, r1, r2, r3, addr)                                            \
    asm volatile("ldmatrix.sync.aligned.m8n8.x4.trans.shared.b16 {%0,%1,%2,%3}, [%4];" \
                 : "=r"(r0), "=r"(r1), "=r"(r2), "=r"(r3) : "r"(addr))
#define MMA_BF16(c0, c1, c2, c3, a0, a1, a2, a3, b0, b1)                          \
    asm volatile(                                                                 \
        "mma.sync.aligned.m16n8k16.row.col.f32.bf16.bf16.f32 "                    \
        "{%0,%1,%2,%3}, {%4,%5,%6,%7}, {%8,%9}, {%0,%1,%2,%3};"                   \
        : "+f"(c0), "+f"(c1), "+f"(c2), "+f"(c3)                                  \
        : "r"(a0), "r"(a1), "r"(a2), "r"(a3), "r"(b0), "r"(b1))

// ---------------- GEMM1: xw1 = x @ W1, pure bf16 tensor cores, pipelined ----------------
#define A_STRIDE 40
#define B_STRIDE 72
#define N_KCHUNK (F_IN / 32)
__global__ __launch_bounds__(256, 2) void gemm1_tc_kernel(const float* __restrict__ x,
                                                          const float* __restrict__ W1) {
    __shared__ __nv_bfloat16 a_sm[128 * A_STRIDE];
    __shared__ __nv_bfloat16 b_sm[32 * B_STRIDE];

    const int tid = threadIdx.x;
    const int wid = tid >> 5;
    const int lane = tid & 31;
    const int nb = blockIdx.x * 128;

    float c[8][4];
#pragma unroll
    for (int j = 0; j < 8; j++)
#pragma unroll
        for (int q = 0; q < 4; q++) c[j][q] = 0.f;

    const int a_row = wid * 16 + (lane & 15);
    const int a_koff = (lane >> 4) * 8;
    const uint32_t a_addr = smem_u32(&a_sm[a_row * A_STRIDE + a_koff]);
    const int b_k = lane & 15;
    const int b_noff = (lane >> 4) * 8;
    const uint32_t b_base = smem_u32(&b_sm[b_k * B_STRIDE + b_noff]);

    const int ar[4] = {(tid + 0) >> 3, (tid + 256) >> 3, (tid + 512) >> 3, (tid + 768) >> 3};
    const int ac = (tid & 7) * 4;
    const int br[2] = {tid >> 4, (tid + 256) >> 4};
    const int bn = (tid & 15) * 4;

    float4 pa[4], pb[2];

#pragma unroll
    for (int j = 0; j < 4; j++) {
        int node = nb + ar[j];
        pa[j] = (node < N_NODES) ? *(const float4*)&x[(size_t)node * F_IN + ac]
                                 : make_float4(0.f, 0.f, 0.f, 0.f);
    }
#pragma unroll
    for (int j = 0; j < 2; j++) pb[j] = *(const float4*)&W1[(size_t)br[j] * F_HID + bn];

    for (int kc = 0; kc < N_KCHUNK; kc++) {
#pragma unroll
        for (int j = 0; j < 4; j++) {
            float4 v = pa[j];
            int r = ar[j];
            *(__nv_bfloat162*)&a_sm[r * A_STRIDE + ac] = __floats2bfloat162_rn(v.x, v.y);
            *(__nv_bfloat162*)&a_sm[r * A_STRIDE + ac + 2] = __floats2bfloat162_rn(v.z, v.w);
        }
#pragma unroll
        for (int j = 0; j < 2; j++) {
            float4 w = pb[j];
            int r = br[j];
            *(__nv_bfloat162*)&b_sm[r * B_STRIDE + bn] = __floats2bfloat162_rn(w.x, w.y);
            *(__nv_bfloat162*)&b_sm[r * B_STRIDE + bn + 2] = __floats2bfloat162_rn(w.z, w.w);
        }
        __syncthreads();

        if (kc + 1 < N_KCHUNK) {
            const int k0n = (kc + 1) * 32;
#pragma unroll
            for (int j = 0; j < 4; j++) {
                int node = nb + ar[j];
                pa[j] = (node < N_NODES) ? *(const float4*)&x[(size_t)node * F_IN + k0n + ac]
                                         : make_float4(0.f, 0.f, 0.f, 0.f);
            }
#pragma unroll
            for (int j = 0; j < 2; j++)
                pb[j] = *(const float4*)&W1[(size_t)(k0n + br[j]) * F_HID + bn];
        }

#pragma unroll
        for (int ks = 0; ks < 2; ks++) {
            uint32_t ah[4];
            LDMATRIX_X4(ah[0], ah[1], ah[2], ah[3], a_addr + ks * 32);
            uint32_t bh[4][4];
#pragma unroll
            for (int nf = 0; nf < 4; nf++) {
                LDMATRIX_X4_T(bh[nf][0], bh[nf][1], bh[nf][2], bh[nf][3],
                              b_base + ks * (16 * B_STRIDE * 2) + nf * 32);
            }
#pragma unroll
            for (int nf = 0; nf < 4; nf++) {
                MMA_BF16(c[2 * nf][0], c[2 * nf][1], c[2 * nf][2], c[2 * nf][3],
                         ah[0], ah[1], ah[2], ah[3], bh[nf][0], bh[nf][1]);
                MMA_BF16(c[2 * nf + 1][0], c[2 * nf + 1][1], c[2 * nf + 1][2], c[2 * nf + 1][3],
                         ah[0], ah[1], ah[2], ah[3], bh[nf][2], bh[nf][3]);
            }
        }
        __syncthreads();
    }

    const int g = lane >> 2;
    const int cl = (lane & 3) * 2;
    const int row0 = nb + wid * 16 + g;
    const int row1 = row0 + 8;
#pragma unroll
    for (int j = 0; j < 8; j++) {
        int col2 = (j * 8 + cl) >> 1;
        if (row0 < N_NODES) g_xw1h[(size_t)row0 * 32 + col2] = __floats2half2_rn(c[j][0], c[j][1]);
        if (row1 < N_NODES) g_xw1h[(size_t)row1 * 32 + col2] = __floats2half2_rn(c[j][2], c[j][3]);
    }
}

// ---------------- init ----------------
__global__ void init_kernel() {
    int i = blockIdx.x * blockDim.x + threadIdx.x;
    if (i < N_NODES) {
        g_deg[i] = 1.0f;
        g_cnt[i] = 0;
    }
}

__global__ void deg_accum_kernel(const int* __restrict__ dst,
                                 const float* __restrict__ ew) {
    int e = blockIdx.x * blockDim.x + threadIdx.x;
    if (e < N_EDGES) {
        int d = dst[e];
        atomicAdd(&g_deg[d], ew[e]);
        atomicAdd(&g_cnt[d], 1);
    }
}

// ---------------- scan ----------------
__global__ void scan1_kernel() {
    __shared__ int sh[SCAN_BLK];
    int i = blockIdx.x * SCAN_BLK + threadIdx.x;
    int t = threadIdx.x;
    int v = (i < N_NODES) ? g_cnt[i] : 0;
    sh[t] = v;
    __syncthreads();
#pragma unroll
    for (int off = 1; off < SCAN_BLK; off <<= 1) {
        int u = (t >= off) ? sh[t - off] : 0;
        __syncthreads();
        sh[t] += u;
        __syncthreads();
    }
    if (i < N_NODES) g_rowstart[i] = sh[t] - v;
    if (t == SCAN_BLK - 1) g_bsum[blockIdx.x] = sh[t];
}

__global__ void scan2_kernel() {
    __shared__ int sh[128];
    int t = threadIdx.x;
    int v = (t < N_SCANB) ? g_bsum[t] : 0;
    sh[t] = v;
    __syncthreads();
#pragma unroll
    for (int off = 1; off < 128; off <<= 1) {
        int u = (t >= off) ? sh[t - off] : 0;
        __syncthreads();
        sh[t] += u;
        __syncthreads();
    }
    if (t < N_SCANB) g_boff[t] = sh[t] - v;
}

// scan3 + dinv + cursor init fused
__global__ void scan3_kernel() {
    int i = blockIdx.x * blockDim.x + threadIdx.x;
    if (i < N_NODES) {
        int rs = g_rowstart[i] + g_boff[i / SCAN_BLK];
        g_rowstart[i] = rs;
        g_cursor[i] = rs;
        g_dinv[i] = rsqrtf(g_deg[i]);
    }
}

__global__ void fill_kernel(const int* __restrict__ src, const int* __restrict__ dst,
                            const float* __restrict__ ew) {
    int e = blockIdx.x * blockDim.x + threadIdx.x;
    if (e >= N_EDGES) return;
    int s = src[e];
    int d = dst[e];
    float nm = g_dinv[s] * ew[e] * g_dinv[d];
    int slot = atomicAdd(&g_cursor[d], 1);
    g_edge[slot] = make_float2(__int_as_float(s), nm);
}

// ---------------- agg1 + gemm2 fused: 8 warps = 8 nodes per block, MLP-8 ----------------
__global__ __launch_bounds__(256) void agg1_gemm2_kernel(const float* __restrict__ b1,
                                                         const float* __restrict__ W2) {
    __shared__ float hs[8][68];
    __shared__ float ws[64][20];
    const int tid = threadIdx.x;
    const int w = tid >> 5;
    const int lane = tid & 31;
    const int n = blockIdx.x * 8 + w;

#pragma unroll
    for (int i = tid; i < 64 * 20; i += 256) ws[i / 20][i % 20] = W2[i];

    if (n < N_NODES) {
        int i = g_rowstart[n];
        int end = i + g_cnt[n];
        float2 acc = make_float2(0.f, 0.f);
        for (; i + 8 <= end; i += 8) {
            float2 e[8];
#pragma unroll
            for (int j = 0; j < 8; j++) e[j] = g_edge[i + j];
            float2 v[8];
#pragma unroll
            for (int j = 0; j < 8; j++)
                v[j] = __half22float2(g_xw1h[(size_t)__float_as_int(e[j].x) * 32 + lane]);
#pragma unroll
            for (int j = 0; j < 8; j++) {
                acc.x = fmaf(e[j].y, v[j].x, acc.x);
                acc.y = fmaf(e[j].y, v[j].y, acc.y);
            }
        }
        for (; i < end; i++) {
            float2 ep = g_edge[i];
            float2 v = __half22float2(g_xw1h[(size_t)__float_as_int(ep.x) * 32 + lane]);
            acc.x = fmaf(ep.y, v.x, acc.x);
            acc.y = fmaf(ep.y, v.y, acc.y);
        }
        float di = g_dinv[n];
        float dd = di * di;
        float2 xv = __half22float2(g_xw1h[(size_t)n * 32 + lane]);
        float2 bv = *(const float2*)&b1[lane * 2];
        hs[w][lane * 2] = fmaxf(bv.x + dd * xv.x + acc.x, 0.f);
        hs[w][lane * 2 + 1] = fmaxf(bv.y + dd * xv.y + acc.y, 0.f);
    }
    __syncthreads();

    if (tid < 160) {
        int nn = tid / 20;
        int o = tid % 20;
        int node = blockIdx.x * 8 + nn;
        if (node < N_NODES) {
            float acc = 0.f;
#pragma unroll
            for (int k = 0; k < 64; k++) acc = fmaf(hs[nn][k], ws[k][o], acc);
            g_h2h[(size_t)node * 32 + o] = __float2half(acc);
        }
    }
}

// ---------------- agg2 + softmax, MLP-8 ----------------
__global__ __launch_bounds__(256) void agg2_kernel(const float* __restrict__ b2,
                                                   float* __restrict__ out) {
    int warp = (blockIdx.x * blockDim.x + threadIdx.x) >> 5;
    int lane = threadIdx.x & 31;
    if (warp >= N_NODES) return;
    int n = warp;
    int i = g_rowstart[n];
    int end = i + g_cnt[n];
    int col = (lane < F_OUT) ? lane : 0;
    float acc = 0.f;
    for (; i + 8 <= end; i += 8) {
        float2 e[8];
#pragma unroll
        for (int j = 0; j < 8; j++) e[j] = g_edge[i + j];
        float v[8];
#pragma unroll
        for (int j = 0; j < 8; j++)
            v[j] = __half2float(g_h2h[(size_t)__float_as_int(e[j].x) * 32 + col]);
#pragma unroll
        for (int j = 0; j < 8; j++) acc = fmaf(e[j].y, v[j], acc);
    }
    for (; i < end; i++) {
        float2 ep = g_edge[i];
        acc = fmaf(ep.y, __half2float(g_h2h[(size_t)__float_as_int(ep.x) * 32 + col]), acc);
    }
    float di = g_dinv[n];
    float dd = di * di;
    float val = -1e30f;
    if (lane < F_OUT)
        val = b2[lane] + dd * __half2float(g_h2h[(size_t)n * 32 + lane]) + acc;
    float m = val;
#pragma unroll
    for (int o = 16; o > 0; o >>= 1) m = fmaxf(m, __shfl_xor_sync(0xFFFFFFFF, m, o));
    float ex = (lane < F_OUT) ? __expf(val - m) : 0.f;
    float s = ex;
#pragma unroll
    for (int o = 16; o > 0; o >>= 1) s += __shfl_xor_sync(0xFFFFFFFF, s, o);
    if (lane < F_OUT) out[(size_t)n * F_OUT + lane] = ex / s;
}

// ---------------- launch ----------------
extern "C" void kernel_launch(void* const* d_in, const int* in_sizes, int n_in,
                              void* d_out, int out_size) {
    const float* x = (const float*)d_in[0];
    const int* ei = (const int*)d_in[1];
    const float* ew = (const float*)d_in[2];
    const float* W1 = (const float*)d_in[3];
    const float* b1 = (const float*)d_in[4];
    const float* W2 = (const float*)d_in[5];
    const float* b2 = (const float*)d_in[6];
    float* out = (float*)d_out;

    const int* src = ei;
    const int* dst = ei + N_EDGES;

    // one-time infra (created on the uncaptured correctness call; reused during capture)
    static cudaStream_t s2 = nullptr;
    static cudaEvent_t ev_fork = nullptr, ev_join = nullptr;
    if (s2 == nullptr) {
        cudaStreamCreateWithFlags(&s2, cudaStreamNonBlocking);
        cudaEventCreateWithFlags(&ev_fork, cudaEventDisableTiming);
        cudaEventCreateWithFlags(&ev_join, cudaEventDisableTiming);
    }

    // fork: gemm1 on s2, overlapped with the CSR pre-pass on the main stream
    cudaEventRecord(ev_fork, 0);
    cudaStreamWaitEvent(s2, ev_fork, 0);
    gemm1_tc_kernel<<<(N_NODES + 127) / 128, 256, 0, s2>>>(x, W1);
    cudaEventRecord(ev_join, s2);

    // pre-pass chain (main stream)
    init_kernel<<<(N_NODES + 255) / 256, 256>>>();
    deg_accum_kernel<<<(N_EDGES + 255) / 256, 256>>>(dst, ew);
    scan1_kernel<<<N_SCANB, SCAN_BLK>>>();
    scan2_kernel<<<1, 128>>>();
    scan3_kernel<<<(N_NODES + 255) / 256, 256>>>();
    fill_kernel<<<(N_EDGES + 255) / 256, 256>>>(src, dst, ew);

    // join: agg1 needs both fill (main) and gemm1 (s2)
    cudaStreamWaitEvent(0, ev_join, 0);
    agg1_gemm2_kernel<<<(N_NODES + 7) / 8, 256>>>(b1, W2);
    agg2_kernel<<<(N_NODES * 32 + 255) / 256, 256>>>(b2, out);
}